// round 2
// baseline (speedup 1.0000x reference)
#include <cuda_runtime.h>
#include <cstdint>

#define BB 4
#define CIN 128
#define CO 64
#define HH 128
#define WW 128
#define HW (HH*WW)

// padded feature plane: y in [0,129] -> row y, x in [0,129] -> col x+3
#define PW 136
#define PH 130
#define PPLANE (PH*PW)

typedef unsigned long long u64;

__device__ __forceinline__ u64 pack2(float lo, float hi) {
    u64 d; asm("mov.b64 %0,{%1,%2};" : "=l"(d) : "f"(lo), "f"(hi)); return d;
}
__device__ __forceinline__ void unpack2(u64 d, float& lo, float& hi) {
    asm("mov.b64 {%0,%1},%2;" : "=f"(lo), "=f"(hi) : "l"(d));
}
#define FMA2(acc,a,b) asm("fma.rn.f32x2 %0,%1,%2,%0;" : "+l"(acc) : "l"(a), "l"(b))

// ---------------- scratch (device globals) ----------------
__device__ float g_yp  [BB*CO*PPLANE];      // padded branch features (zero ring)
__device__ float g_off [BB*18*HW];          // offsets
__device__ float g_f   [BB*4*CO*HW];        // combined deform features
__device__ float g_wtbd[4*CIN*9*128];       // branch w, dup pairs: [br][ic*9+tap][4ocg*32]
__device__ float g_wtpd[CO*9*64];           // p_w dup: [ic*9+tap][2ocg*32]
__device__ float g_dwtd[CO*9*128];          // dw dup: [c*9+n][oc dup 128]
__device__ float g_cwtd[4*CO*128];          // cw dup: [k][oc dup 128]

// ---------------- prep: weight transpose+duplicate, ring zero ----------------
__global__ void prep_kernel(const float* __restrict__ w1, const float* __restrict__ w2,
                            const float* __restrict__ w3, const float* __restrict__ w4,
                            const float* __restrict__ pw, const float* __restrict__ dwp,
                            const float* __restrict__ cwp)
{
    int tid = blockIdx.x*blockDim.x + threadIdx.x;
    int nt  = gridDim.x*blockDim.x;
    const float* wb[4] = {w1,w2,w3,w4};
    for (int i = tid; i < 4*1152*128; i += nt) {
        int br = i/(1152*128); int r2 = i%(1152*128);
        int row = r2>>7; int q = r2&127;
        int oc = (q>>5)*16 + ((q&31)>>1);
        g_wtbd[i] = wb[br][oc*1152 + row];
    }
    for (int i = tid; i < 576*64; i += nt) {
        int row = i>>6; int q = i&63;
        int oc = (q>>5)*16 + ((q&31)>>1);
        g_wtpd[i] = (oc < 18) ? pw[oc*576 + row] : 0.f;
    }
    for (int i = tid; i < 576*128; i += nt) {
        int row = i>>7; int oc = (i&127)>>1;
        g_dwtd[i] = dwp[oc*576 + row];
    }
    for (int i = tid; i < 256*128; i += nt) {
        int row = i>>7; int oc = (i&127)>>1;
        g_cwtd[i] = cwp[oc*256 + row];
    }
    // zero ring of padded planes: rows 0,129 full; cols 3,132 for rows 1..128
    for (int i = tid; i < 256*528; i += nt) {
        int p = i/528; int j = i - p*528;
        int r, c;
        if (j < 136)      { r = 0;        c = j; }
        else if (j < 272) { r = 129;      c = j - 136; }
        else if (j < 400) { r = j - 271;  c = 3; }
        else              { r = j - 399;  c = 132; }
        g_yp[(size_t)p*PPLANE + r*PW + c] = 0.f;
    }
}

// ---------------- dilated 3x3 conv, packed f32x2, ic-chunked ----------------
// MODE 0: input x (B,128,H,W) -> g_yp padded, scaled.  MODE 1: input g_yp -> g_off (18ch).
template<int D, int MODE>
__global__ void conv3x3_kernel(const float* __restrict__ xin,
                               const float* __restrict__ wsrc,
                               const float* __restrict__ bias, float scale)
{
    constexpr int XW  = 32 + 2*D;
    constexpr int SXW = XW + 1;
    constexpr int SXH = 16 + 2*D;
    constexpr int CI  = MODE ? 64 : 128;
    constexpr int WST = MODE ? 64 : 128;
    __shared__ __align__(16) float sx[4][SXH*SXW];
    __shared__ __align__(16) float swd[4*9*32];

    int tx = threadIdx.x, ty = threadIdx.y;
    int tid = ty*8 + tx;
    int col0 = blockIdx.x*32, row0 = blockIdx.y*16;
    int b, ocg;
    if (MODE) { b = blockIdx.z >> 1; ocg = blockIdx.z & 1; }
    else      { b = blockIdx.z >> 2; ocg = blockIdx.z & 3; }
    int oc0 = ocg*16;
    const float* wbase = wsrc + ocg*32;
    const float* xb0 = MODE ? (g_yp + (size_t)b*CO*PPLANE)
                            : (xin + (size_t)b*CI*HW);

    u64 acc[16][2];
    #pragma unroll
    for (int i = 0; i < 16; i++) { acc[i][0] = 0ull; acc[i][1] = 0ull; }

    for (int ic0 = 0; ic0 < CI; ic0 += 4) {
        #pragma unroll 1
        for (int u = tid; u < 4*SXH*XW; u += 128) {
            int icl = u/(SXH*XW); int rem = u - icl*(SXH*XW);
            int rr = rem/XW; int cc2 = rem - rr*XW;
            int gy = row0 + rr - D, gx = col0 + cc2 - D;
            float v;
            if (MODE) {
                v = xb0[(size_t)(ic0+icl)*PPLANE + (gy+1)*PW + gx+4];
            } else {
                v = ((unsigned)gy < 128u && (unsigned)gx < 128u)
                    ? xb0[(size_t)(ic0+icl)*HW + gy*WW + gx] : 0.f;
            }
            sx[icl][rr*SXW + cc2] = v;
        }
        #pragma unroll 1
        for (int i = tid; i < 288; i += 128) {
            int rowl = i >> 3, j = i & 7;
            *(float4*)&swd[rowl*32 + j*4] =
                *(const float4*)&wbase[(size_t)(ic0*9 + rowl)*WST + j*4];
        }
        __syncthreads();
        #pragma unroll
        for (int icl = 0; icl < 4; icl++) {
            const float* sxp = sx[icl];
            #pragma unroll
            for (int ky = 0; ky < 3; ky++) {
                #pragma unroll
                for (int kx = 0; kx < 3; kx++) {
                    const float* xr = &sxp[(ty + ky*D)*SXW + tx*4 + kx*D];
                    u64 x01 = pack2(xr[0], xr[1]);
                    u64 x23 = pack2(xr[2], xr[3]);
                    const ulonglong2* wq = (const ulonglong2*)&swd[(icl*9 + ky*3 + kx)*32];
                    #pragma unroll
                    for (int j = 0; j < 8; j++) {
                        ulonglong2 wv = wq[j];
                        FMA2(acc[2*j  ][0], wv.x, x01); FMA2(acc[2*j  ][1], wv.x, x23);
                        FMA2(acc[2*j+1][0], wv.y, x01); FMA2(acc[2*j+1][1], wv.y, x23);
                    }
                }
            }
        }
        __syncthreads();
    }

    int h = row0 + ty, w = col0 + tx*4;
    #pragma unroll
    for (int o = 0; o < 16; o++) {
        int oc = oc0 + o;
        float bb = MODE ? ((oc < 18) ? bias[oc] : 0.f) : bias[oc];
        float a0,a1,a2,a3;
        unpack2(acc[o][0], a0, a1); unpack2(acc[o][1], a2, a3);
        float4 r = make_float4((a0+bb)*scale, (a1+bb)*scale, (a2+bb)*scale, (a3+bb)*scale);
        if (MODE) {
            if (oc < 18)
                *(float4*)&g_off[(((size_t)(b*18 + oc))*HH + h)*WW + w] = r;
        } else {
            *(float4*)&g_yp[(size_t)(b*CO + oc)*PPLANE + (size_t)(h+1)*PW + w + 4] = r;
        }
    }
}

// ---------------- deformable sampling + matmul, packed, padded gathers ----------------
__global__ void deform_kernel(const float* __restrict__ db, int br)
{
    __shared__ int   sit[576], sib[576];
    __shared__ float sg0[576], sg1[576], sg2[576], sg3[576];
    __shared__ __align__(16) float ssmp[2304];     // [4c][9n][64px]
    __shared__ __align__(16) float sdwd[36*128];   // dup weights, 4-ch chunk

    int tid = threadIdx.x;
    int w0  = blockIdx.x*64;
    int h   = blockIdx.y;
    int b   = blockIdx.z;

    #pragma unroll 1
    for (int t = tid; t < 576; t += 256) {
        int n = t >> 6, px = t & 63;
        int wg = w0 + px;
        const float* offp = g_off + (((size_t)(b*18 + n))*HH + h)*WW + wg;
        float offy = offp[0];
        float offx = offp[9*HW];
        float py  = (float)(h + 1)  + (float)(n/3) - 1.f + offy;
        float pxx = (float)(wg + 1) + (float)(n%3) - 1.f + offx;
        float fy = floorf(py), fx = floorf(pxx);
        float pyc = fminf(fmaxf(py,  0.f), 129.f);
        float pxc = fminf(fmaxf(pxx, 0.f), 129.f);
        float lty = fminf(fmaxf(fy,       0.f), 129.f);
        float rby = fminf(fmaxf(fy + 1.f, 0.f), 129.f);
        float ltx = fminf(fmaxf(fx,       0.f), 129.f);
        float rbx = fminf(fmaxf(fx + 1.f, 0.f), 129.f);
        float gy1 = 1.f + (lty - pyc), gy2 = 1.f - (rby - pyc);
        float gx1 = 1.f + (ltx - pxc), gx2 = 1.f - (rbx - pxc);
        if (!(fx >= 0.f && fx <= 128.f)) { gx1 = 0.f; gx2 = 0.f; }
        int x0b = min(max((int)fx, 0), 128);
        int y0 = (int)lty, y1 = (int)rby;
        sit[t] = y0*PW + x0b + 3;
        sib[t] = y1*PW + x0b + 3;
        sg0[t] = gy1*gx1;   // (y0,x0)
        sg1[t] = gy1*gx2;   // (y0,x1)
        sg2[t] = gy2*gx1;   // (y1,x0)
        sg3[t] = gy2*gx2;   // (y1,x1)
    }

    int qp = tid & 15, qo = tid >> 4;
    u64 acc[4][2];
    #pragma unroll
    for (int i = 0; i < 4; i++) { acc[i][0] = 0ull; acc[i][1] = 0ull; }
    const float* ypb = g_yp + (size_t)b*CO*PPLANE;
    __syncthreads();

    for (int c0 = 0; c0 < CO; c0 += 4) {
        #pragma unroll 1
        for (int i = tid; i < 1152; i += 256)
            *(float4*)&sdwd[i*4] = *(const float4*)&g_dwtd[(size_t)c0*9*128 + i*4];
        #pragma unroll
        for (int cc = 0; cc < 4; cc++) {
            const float* bp = ypb + (size_t)(c0 + cc)*PPLANE;
            #pragma unroll 1
            for (int v = tid; v < 576; v += 256) {
                int it = sit[v], ib = sib[v];
                float T0 = bp[it], T1 = bp[it+1], B0 = bp[ib], B1 = bp[ib+1];
                ssmp[cc*576 + v] = sg0[v]*T0 + sg1[v]*T1 + sg2[v]*B0 + sg3[v]*B1;
            }
        }
        __syncthreads();
        #pragma unroll 4
        for (int r = 0; r < 36; r++) {
            ulonglong2 sv  = *(const ulonglong2*)&ssmp[r*64 + qp*4];
            ulonglong2 w01 = *(const ulonglong2*)&sdwd[r*128 + qo*8];
            ulonglong2 w23 = *(const ulonglong2*)&sdwd[r*128 + qo*8 + 4];
            FMA2(acc[0][0], w01.x, sv.x); FMA2(acc[0][1], w01.x, sv.y);
            FMA2(acc[1][0], w01.y, sv.x); FMA2(acc[1][1], w01.y, sv.y);
            FMA2(acc[2][0], w23.x, sv.x); FMA2(acc[2][1], w23.x, sv.y);
            FMA2(acc[3][0], w23.y, sv.x); FMA2(acc[3][1], w23.y, sv.y);
        }
        __syncthreads();
    }

    int wq = w0 + qp*4;
    #pragma unroll
    for (int i = 0; i < 4; i++) {
        int oc = qo*4 + i;
        float bb = db[oc];
        float a0,a1,a2,a3;
        unpack2(acc[i][0], a0, a1); unpack2(acc[i][1], a2, a3);
        float4 r = make_float4(a0+bb, a1+bb, a2+bb, a3+bb);
        *(float4*)&g_f[((size_t)(b*4*CO + br*CO + oc))*HW + h*WW + wq] = r;
    }
}

// ---------------- final 1x1 conv (256->64) + ReLU, packed ----------------
__global__ void final_kernel(const float* __restrict__ cb, float* __restrict__ out)
{
    __shared__ __align__(16) float fs[1024];    // [16k][64px]
    __shared__ __align__(16) float wsd[2048];   // [16k][oc dup 128]
    int tid = threadIdx.x;
    int p0  = blockIdx.x*64;
    int b   = blockIdx.y;
    int qp = tid & 15, qo = tid >> 4;

    u64 acc[4][2];
    #pragma unroll
    for (int i = 0; i < 4; i++) { acc[i][0] = 0ull; acc[i][1] = 0ull; }

    for (int k0 = 0; k0 < 256; k0 += 16) {
        {
            int i = tid*4;
            int kk = i >> 6, px = i & 63;
            *(float4*)&fs[i] = *(const float4*)&g_f[((size_t)(b*256 + k0 + kk))*HW + p0 + px];
        }
        #pragma unroll 1
        for (int i = tid; i < 512; i += 256)
            *(float4*)&wsd[i*4] = *(const float4*)&g_cwtd[(size_t)k0*128 + i*4];
        __syncthreads();
        #pragma unroll
        for (int kk = 0; kk < 16; kk++) {
            ulonglong2 sv  = *(const ulonglong2*)&fs[kk*64 + qp*4];
            ulonglong2 w01 = *(const ulonglong2*)&wsd[kk*128 + qo*8];
            ulonglong2 w23 = *(const ulonglong2*)&wsd[kk*128 + qo*8 + 4];
            FMA2(acc[0][0], w01.x, sv.x); FMA2(acc[0][1], w01.x, sv.y);
            FMA2(acc[1][0], w01.y, sv.x); FMA2(acc[1][1], w01.y, sv.y);
            FMA2(acc[2][0], w23.x, sv.x); FMA2(acc[2][1], w23.x, sv.y);
            FMA2(acc[3][0], w23.y, sv.x); FMA2(acc[3][1], w23.y, sv.y);
        }
        __syncthreads();
    }

    int pp = p0 + qp*4;
    #pragma unroll
    for (int i = 0; i < 4; i++) {
        int oc = qo*4 + i;
        float bb = cb[oc];
        float a0,a1,a2,a3;
        unpack2(acc[i][0], a0, a1); unpack2(acc[i][1], a2, a3);
        float4 r = make_float4(fmaxf(a0+bb,0.f), fmaxf(a1+bb,0.f),
                               fmaxf(a2+bb,0.f), fmaxf(a3+bb,0.f));
        *(float4*)&out[((size_t)(b*CO + oc))*HW + pp] = r;
    }
}

// ---------------- launch ----------------
extern "C" void kernel_launch(void* const* d_in, const int* in_sizes, int n_in,
                              void* d_out, int out_size)
{
    const float* x   = (const float*)d_in[0];
    const float* w1  = (const float*)d_in[1];
    const float* b1  = (const float*)d_in[2];
    const float* w2  = (const float*)d_in[3];
    const float* b2  = (const float*)d_in[4];
    const float* w3  = (const float*)d_in[5];
    const float* b3  = (const float*)d_in[6];
    const float* w4  = (const float*)d_in[7];
    const float* b4  = (const float*)d_in[8];
    const float* p_w = (const float*)d_in[9];
    const float* p_b = (const float*)d_in[10];
    const float* dw  = (const float*)d_in[11];
    const float* db  = (const float*)d_in[12];
    const float* cw  = (const float*)d_in[13];
    const float* cb  = (const float*)d_in[14];
    float* out = (float*)d_out;

    prep_kernel<<<256, 256>>>(w1, w2, w3, w4, p_w, dw, cw);

    float* wtbd_base;
    cudaGetSymbolAddress((void**)&wtbd_base, g_wtbd);
    float* wtpd_base;
    cudaGetSymbolAddress((void**)&wtpd_base, g_wtpd);

    dim3 cblk(8, 16);
    dim3 gbr(4, 8, 16);
    dim3 goff(4, 8, 8);
    dim3 gdef(2, 128, 4);

    const float* bias[4] = {b1, b2, b3, b4};
    for (int br = 0; br < 4; br++) {
        float s = (float)(2*br + 1);
        const float* wsrc = wtbd_base + (size_t)br*1152*128;
        switch (br) {
            case 0: conv3x3_kernel<1,0><<<gbr, cblk>>>(x, wsrc, bias[0], s); break;
            case 1: conv3x3_kernel<3,0><<<gbr, cblk>>>(x, wsrc, bias[1], s); break;
            case 2: conv3x3_kernel<5,0><<<gbr, cblk>>>(x, wsrc, bias[2], s); break;
            case 3: conv3x3_kernel<7,0><<<gbr, cblk>>>(x, wsrc, bias[3], s); break;
        }
        conv3x3_kernel<1,1><<<goff, cblk>>>(x, wtpd_base, p_b, 1.f);
        deform_kernel<<<gdef, 256>>>(db, br);
    }
    final_kernel<<<dim3(256, 4), 256>>>(cb, out);
}

// round 4
// speedup vs baseline: 1.8809x; 1.8809x over previous
#include <cuda_runtime.h>
#include <cuda_bf16.h>
#include <cstdint>

#define BB 4
#define CIN 128
#define CO 64
#define HH 128
#define WW 128
#define HW (HH*WW)

#define PW 136
#define PH 130
#define PPLANE (PH*PW)

#define PLANE_WW 80
#define PLANE_RR 142
#define PLANE_SZ (PLANE_RR*PLANE_WW)

typedef unsigned long long u64;
typedef unsigned int u32;

__device__ __forceinline__ u32 smem_to_u32(const void* p) {
    u32 a; asm("{ .reg .u64 t; cvta.to.shared.u64 t, %1; cvt.u32.u64 %0, t; }" : "=r"(a) : "l"(p));
    return a;
}

// packed fp32 helpers (deform/offconv/final)
__device__ __forceinline__ u64 pack2(float lo, float hi) {
    u64 d; asm("mov.b64 %0,{%1,%2};" : "=l"(d) : "f"(lo), "f"(hi)); return d;
}
__device__ __forceinline__ void unpack2(u64 d, float& lo, float& hi) {
    asm("mov.b64 {%0,%1},%2;" : "=f"(lo), "=f"(hi) : "l"(d));
}
#define FMA2(acc,a,b) asm("fma.rn.f32x2 %0,%1,%2,%0;" : "+l"(acc) : "l"(a), "l"(b))

#define MMA_BF16(d0,d1,d2,d3,a0,a1,a2,a3,b0,b1) \
    asm volatile("mma.sync.aligned.m16n8k16.row.col.f32.bf16.bf16.f32 " \
        "{%0,%1,%2,%3},{%4,%5,%6,%7},{%8,%9},{%0,%1,%2,%3};" \
        : "+f"(d0),"+f"(d1),"+f"(d2),"+f"(d3) \
        : "r"(a0),"r"(a1),"r"(a2),"r"(a3),"r"(b0),"r"(b1))

#define LDMATRIX_X4_TRANS(r0,r1,r2,r3,addr) \
    asm volatile("ldmatrix.sync.aligned.m8n8.x4.trans.shared.b16 {%0,%1,%2,%3},[%4];" \
        : "=r"(r0),"=r"(r1),"=r"(r2),"=r"(r3) : "r"(addr))

// ================= scratch =================
__device__ u32   g_xs  [2*2*4*128*PLANE_SZ];   // [split][phase][b][ic] padded bf16-pair planes
__device__ u32   g_wfA [4*72*8*32*4];          // A fragments [br][ks][mb][lane][reg]
__device__ float g_bias[4*64];
__device__ float g_yp  [16*64*PPLANE];         // (br*4+b) padded features, zero ring
__device__ float g_off [16*18*HW];
__device__ float g_f   [4*256*HW];
__device__ float g_wtpd[576*64];
__device__ float g_dwtd[576*128];
__device__ float g_cwtd[256*128];

// ================= prep 1 =================
__global__ void prep1_kernel(const float* __restrict__ w1, const float* __restrict__ w2,
                             const float* __restrict__ w3, const float* __restrict__ w4,
                             const float* __restrict__ pw, const float* __restrict__ dwp,
                             const float* __restrict__ cwp,
                             const float* __restrict__ b1, const float* __restrict__ b2,
                             const float* __restrict__ b3, const float* __restrict__ b4)
{
    int tid = blockIdx.x*blockDim.x + threadIdx.x;
    int nt  = gridDim.x*blockDim.x;
    const float* wb[4] = {w1,w2,w3,w4};
    const float* bbv[4] = {b1,b2,b3,b4};

    // A fragments: m16n8k16 register layout, u32 = (bf16 k, bf16 k+1)
    for (int i = tid; i < 4*72*8*32*4; i += nt) {
        int br = i / 73728; int r2 = i % 73728;
        int ks = r2 >> 10;  int r3 = r2 & 1023;
        int mb = r3 >> 7;   int lane = (r3 >> 2) & 31; int reg = r3 & 3;
        int row = mb*16 + (lane>>2) + (reg&1)*8;
        int k0  = (lane&3)*2 + (reg>>1)*8;
        int oc = row & 63, split = row >> 6;
        int tap = ks >> 3;
        int ic0 = (ks & 7)*16;
        u32 out = 0;
        #pragma unroll
        for (int e = 0; e < 2; e++) {
            float W = wb[br][oc*1152 + (ic0 + k0 + e)*9 + tap];
            __nv_bfloat16 hi = __float2bfloat16(W);
            __nv_bfloat16 v = split ? __float2bfloat16(W - __bfloat162float(hi)) : hi;
            out |= (u32)__bfloat16_as_ushort(v) << (16*e);
        }
        g_wfA[i] = out;
    }
    for (int i = tid; i < 256; i += nt) g_bias[i] = bbv[i>>6][i&63];
    for (int i = tid; i < 576*64; i += nt) {
        int row = i>>6; int q = i&63;
        int oc = (q>>5)*16 + ((q&31)>>1);
        g_wtpd[i] = (oc < 18) ? pw[oc*576 + row] : 0.f;
    }
    for (int i = tid; i < 576*128; i += nt) {
        int row = i>>7; int oc = (i&127)>>1;
        g_dwtd[i] = dwp[oc*576 + row];
    }
    for (int i = tid; i < 256*128; i += nt) {
        int row = i>>7; int oc = (i&127)>>1;
        g_cwtd[i] = cwp[oc*256 + row];
    }
    // zero ring of all 1024 padded feature planes
    for (int i = tid; i < 1024*528; i += nt) {
        int p = i/528; int j = i - p*528;
        int r, c;
        if (j < 136)      { r = 0;       c = j; }
        else if (j < 272) { r = 129;     c = j - 136; }
        else if (j < 400) { r = j - 271; c = 3; }
        else              { r = j - 399; c = 132; }
        g_yp[(size_t)p*PPLANE + r*PW + c] = 0.f;
    }
}

// ================= prep 2: padded bf16 split/phase x planes =================
__global__ void prep2_kernel(const float* __restrict__ x)
{
    size_t total = (size_t)2*2*4*128*PLANE_SZ;
    size_t stride = (size_t)gridDim.x*blockDim.x;
    for (size_t i = (size_t)blockIdx.x*blockDim.x + threadIdx.x; i < total; i += stride) {
        int wd = (int)(i % PLANE_WW); size_t t = i / PLANE_WW;
        int rr = (int)(t % PLANE_RR); t /= PLANE_RR;
        int ic = (int)(t % 128); t /= 128;
        int b  = (int)(t % 4);   t /= 4;
        int phase = (int)(t & 1); int split = (int)(t >> 1);
        int row = rr - 7;
        int pxa = 2*wd + phase - 8;
        float va = 0.f, vb = 0.f;
        if ((unsigned)row < 128u) {
            const float* xr = x + ((size_t)(b*128+ic)*128 + row)*128;
            if ((unsigned)pxa < 128u)     va = xr[pxa];
            if ((unsigned)(pxa+1) < 128u) vb = xr[pxa+1];
        }
        __nv_bfloat16 ba, bbv;
        if (split == 0) { ba = __float2bfloat16(va); bbv = __float2bfloat16(vb); }
        else {
            ba  = __float2bfloat16(va - __bfloat162float(__float2bfloat16(va)));
            bbv = __float2bfloat16(vb - __bfloat162float(__float2bfloat16(vb)));
        }
        g_xs[i] = (u32)__bfloat16_as_ushort(ba) | ((u32)__bfloat16_as_ushort(bbv) << 16);
    }
}

// ================= branch conv: mma.sync bf16 hi/lo split =================
// grid (128 h, 4 br, 4 b), 256 thr = 8 warps: wm = wid%4 (M: 32 rows), nw = wid/4 (N: 64 px)
// A rows 0-63 = wh(oc), 64-127 = wl(oc). wh-warps: 2 MMAs/acc (B=xh,xl); wl-warps: 1 (xh).
__global__ void __launch_bounds__(256,2) bconv_kernel()
{
    __shared__ __align__(16) char sraw[33280];
    // B buffers: [buf2][split2][ic16][136 bf16]  (8704 B per buf)
    u32 sb = smem_to_u32(sraw);

    int tid = threadIdx.x, wid = tid>>5, lane = tid&31;
    int wm = wid & 3, nw = wid >> 2;
    int h = blockIdx.x, br = blockIdx.y, b = blockIdx.z;
    int D = 2*br + 1; float scale = (float)D;
    bool is_wh = (wm < 2);

    float acc[2][8][4];
    #pragma unroll
    for (int mi = 0; mi < 2; mi++)
        #pragma unroll
        for (int ni = 0; ni < 8; ni++)
            #pragma unroll
            for (int r = 0; r < 4; r++) acc[mi][ni][r] = 0.f;

    // ldmatrix base addrs for this thread (per split, per n16 block)
    int lm_mat = lane >> 3, lm_row = lane & 7;
    int lm_k = (lm_mat & 1)*8 + lm_row;
    int lm_noff = (lm_mat >> 1)*8;

    // ---- B loader closure data ----
    // per k-step: tap = ks>>3 (ky=tap/3-1, kx=tap%3-1), icc = ks&7
    // planes: g_xs[((split*2+phase)*4 + b)*128 + ic] ; row srow, u32 col wd0+j
    auto loadB = [&](int ks, int buf) {
        int tap = ks >> 3, icc = ks & 7;
        int ky = tap/3 - 1, kx = tap - (tap/3)*3 - 1;
        int s = kx*D;
        int phase = (s + 8) & 1;
        int wd0 = (s + 8 - phase) >> 1;
        int srow = h + ky*D + 7;
        char* dst = sraw + buf*8704;
        #pragma unroll
        for (int i = 0; i < 8; i++) {
            int idx = tid + 256*i;
            int split = idx >> 10; int rem = idx & 1023;
            int ic = rem >> 6; int j = rem & 63;
            const u32* p = g_xs + ((size_t)((split*2+phase)*4 + b)*128 + icc*16 + ic)*PLANE_SZ
                         + (size_t)srow*PLANE_WW + wd0 + j;
            u32 v = __ldg(p);
            *(u32*)(dst + split*4352 + ic*272 + j*4) = v;
        }
    };

    loadB(0, 0);
    __syncthreads();

    for (int ks = 0; ks < 72; ks++) {
        int buf = ks & 1;
        if (ks + 1 < 72) loadB(ks+1, buf^1);

        // A fragments (2 m16 blocks), direct LDG, pre-laid layout
        u32 a0[2][4];
        {
            const uint4* ap = (const uint4*)(g_wfA + (((size_t)(br*72 + ks)*8 + wm*2)*32 + lane)*4);
            uint4 f0 = ap[0];      // mb = 2*wm
            uint4 f1 = ap[32];     // mb = 2*wm+1  (32 lanes * 16B ahead)
            a0[0][0]=f0.x; a0[0][1]=f0.y; a0[0][2]=f0.z; a0[0][3]=f0.w;
            a0[1][0]=f1.x; a0[1][1]=f1.y; a0[1][2]=f1.z; a0[1][3]=f1.w;
        }

        int nsplits = is_wh ? 2 : 1;
        for (int sp = 0; sp < nsplits; sp++) {
            u32 bf[8][2];
            u32 base = sb + buf*8704 + sp*4352 + lm_k*272;
            #pragma unroll
            for (int li = 0; li < 4; li++) {
                int n = nw*64 + li*16 + lm_noff;
                u32 r0,r1,r2,r3;
                LDMATRIX_X4_TRANS(r0,r1,r2,r3, base + n*2);
                bf[2*li][0]=r0; bf[2*li][1]=r1; bf[2*li+1][0]=r2; bf[2*li+1][1]=r3;
            }
            #pragma unroll
            for (int mi = 0; mi < 2; mi++)
                #pragma unroll
                for (int ni = 0; ni < 8; ni++)
                    MMA_BF16(acc[mi][ni][0],acc[mi][ni][1],acc[mi][ni][2],acc[mi][ni][3],
                             a0[mi][0],a0[mi][1],a0[mi][2],a0[mi][3],
                             bf[ni][0],bf[ni][1]);
        }
        __syncthreads();
    }

    // ---- epilogue: combine wh + wl, add bias, scale, write g_yp ----
    float* epi = (float*)sraw;
    if (!is_wh) {
        int pair = nw*2 + (wm - 2);
        #pragma unroll
        for (int mi = 0; mi < 2; mi++)
            #pragma unroll
            for (int ni = 0; ni < 8; ni++)
                *(float4*)&epi[pair*2048 + (mi*8+ni)*128 + lane*4] = *(float4*)acc[mi][ni];
    }
    __syncthreads();
    if (is_wh) {
        int pair = nw*2 + wm;
        int bi = br*4 + b;
        #pragma unroll
        for (int mi = 0; mi < 2; mi++) {
            #pragma unroll
            for (int ni = 0; ni < 8; ni++) {
                float4 part = *(float4*)&epi[pair*2048 + (mi*8+ni)*128 + lane*4];
                int oc = wm*32 + mi*16 + (lane>>2);
                int px = nw*64 + ni*8 + (lane&3)*2;
                float bb0 = g_bias[br*64 + oc];
                float bb8 = g_bias[br*64 + oc + 8];
                float* p0 = g_yp + ((size_t)(bi*64 + oc))*PPLANE + (size_t)(h+1)*PW + px + 4;
                float* p8 = p0 + (size_t)8*PPLANE;
                float2 o0, o8;
                o0.x = (acc[mi][ni][0] + part.x + bb0)*scale;
                o0.y = (acc[mi][ni][1] + part.y + bb0)*scale;
                o8.x = (acc[mi][ni][2] + part.z + bb8)*scale;
                o8.y = (acc[mi][ni][3] + part.w + bb8)*scale;
                *(float2*)p0 = o0;
                *(float2*)p8 = o8;
            }
        }
    }
}

// ================= offset conv (3x3, d=1, 64->18) =================
__global__ void offconv_kernel(const float* __restrict__ bias)
{
    constexpr int XW  = 34, SXW = 35, SXH = 18;
    __shared__ __align__(16) float sx[4][SXH*SXW];
    __shared__ __align__(16) float swd[4*9*32];

    int tx = threadIdx.x, ty = threadIdx.y;
    int tid = ty*8 + tx;
    int col0 = blockIdx.x*32, row0 = blockIdx.y*16;
    int bi = blockIdx.z >> 1;
    int ocg = blockIdx.z & 1;
    int oc0 = ocg*16;
    const float* wbase = g_wtpd + ocg*32;
    const float* xb0 = g_yp + (size_t)bi*CO*PPLANE;

    u64 acc[16][2];
    #pragma unroll
    for (int i = 0; i < 16; i++) { acc[i][0] = 0ull; acc[i][1] = 0ull; }

    for (int ic0 = 0; ic0 < 64; ic0 += 4) {
        #pragma unroll 1
        for (int u = tid; u < 4*SXH*XW; u += 128) {
            int icl = u/(SXH*XW); int rem = u - icl*(SXH*XW);
            int rr = rem/XW; int cc2 = rem - rr*XW;
            int gy = row0 + rr - 1, gx = col0 + cc2 - 1;
            sx[icl][rr*SXW + cc2] = xb0[(size_t)(ic0+icl)*PPLANE + (gy+1)*PW + gx+4];
        }
        #pragma unroll 1
        for (int i = tid; i < 288; i += 128) {
            int rowl = i >> 3, j = i & 7;
            *(float4*)&swd[rowl*32 + j*4] =
                *(const float4*)&wbase[(size_t)(ic0*9 + rowl)*64 + j*4];
        }
        __syncthreads();
        #pragma unroll
        for (int icl = 0; icl < 4; icl++) {
            const float* sxp = sx[icl];
            #pragma unroll
            for (int ky = 0; ky < 3; ky++) {
                #pragma unroll
                for (int kx = 0; kx < 3; kx++) {
                    const float* xr = &sxp[(ty + ky)*SXW + tx*4 + kx];
                    u64 x01 = pack2(xr[0], xr[1]);
                    u64 x23 = pack2(xr[2], xr[3]);
                    const ulonglong2* wq = (const ulonglong2*)&swd[(icl*9 + ky*3 + kx)*32];
                    #pragma unroll
                    for (int j = 0; j < 8; j++) {
                        ulonglong2 wv = wq[j];
                        FMA2(acc[2*j  ][0], wv.x, x01); FMA2(acc[2*j  ][1], wv.x, x23);
                        FMA2(acc[2*j+1][0], wv.y, x01); FMA2(acc[2*j+1][1], wv.y, x23);
                    }
                }
            }
        }
        __syncthreads();
    }

    int h = row0 + ty, w = col0 + tx*4;
    #pragma unroll
    for (int o = 0; o < 16; o++) {
        int oc = oc0 + o;
        if (oc < 18) {
            float bb = bias[oc];
            float a0,a1,a2,a3;
            unpack2(acc[o][0], a0, a1); unpack2(acc[o][1], a2, a3);
            float4 r = make_float4(a0+bb, a1+bb, a2+bb, a3+bb);
            *(float4*)&g_off[(((size_t)(bi*18 + oc))*HH + h)*WW + w] = r;
        }
    }
}

// ================= deformable sampling + matmul =================
__global__ void deform_kernel(const float* __restrict__ db)
{
    __shared__ int   sit[576], sib[576];
    __shared__ float sg0[576], sg1[576], sg2[576], sg3[576];
    __shared__ __align__(16) float ssmp[2304];
    __shared__ __align__(16) float sdwd[36*128];

    int tid = threadIdx.x;
    int w0  = blockIdx.x*64;
    int h   = blockIdx.y;
    int bi  = blockIdx.z;
    int br  = bi >> 2, b = bi & 3;

    #pragma unroll 1
    for (int t = tid; t < 576; t += 256) {
        int n = t >> 6, px = t & 63;
        int wg = w0 + px;
        const float* offp = g_off + (((size_t)(bi*18 + n))*HH + h)*WW + wg;
        float offy = offp[0];
        float offx = offp[9*HW];
        float py  = (float)(h + 1)  + (float)(n/3) - 1.f + offy;
        float pxx = (float)(wg + 1) + (float)(n%3) - 1.f + offx;
        float fy = floorf(py), fx = floorf(pxx);
        float pyc = fminf(fmaxf(py,  0.f), 129.f);
        float pxc = fminf(fmaxf(pxx, 0.f), 129.f);
        float lty = fminf(fmaxf(fy,       0.f), 129.f);
        float rby = fminf(fmaxf(fy + 1.f, 0.f), 129.f);
        float ltx = fminf(fmaxf(fx,       0.f), 129.f);
        float rbx = fminf(fmaxf(fx + 1.f, 0.f), 129.f);
        float gy1 = 1.f + (lty - pyc), gy2 = 1.f - (rby - pyc);
        float gx1 = 1.f + (ltx - pxc), gx2 = 1.f - (rbx - pxc);
        if (!(fx >= 0.f && fx <= 128.f)) { gx1 = 0.f; gx2 = 0.f; }
        int x0b = min(max((int)fx, 0), 128);
        int y0 = (int)lty, y1 = (int)rby;
        sit[t] = y0*PW + x0b + 3;
        sib[t] = y1*PW + x0b + 3;
        sg0[t] = gy1*gx1;
        sg1[t] = gy1*gx2;
        sg2[t] = gy2*gx1;
        sg3[t] = gy2*gx2;
    }

    int qp = tid & 15, qo = tid >> 4;
    u64 acc[4][2];
    #pragma unroll
    for (int i = 0; i < 4; i++) { acc[i][0] = 0ull; acc[i][1] = 0ull; }
    const float* ypb = g_yp + (size_t)bi*CO*PPLANE;
    __syncthreads();

    for (int c0 = 0; c0 < CO; c0 += 4) {
        #pragma unroll 1
        for (int i = tid; i < 1152; i += 256)
            *(float4*)&sdwd[i*4] = *(const float4*)&g_dwtd[(size_t)c0*9*128 + i*4];
        #pragma unroll
        for (int cc = 0; cc < 4; cc++) {
            const float* bp = ypb + (size_t)(c0 + cc)*PPLANE;
            #pragma unroll 1
            for (int v = tid; v < 576; v += 256) {
                int it = sit[v], ib = sib[v];
                float T0 = bp[it], T1 = bp[it+1], B0 = bp[ib], B1 = bp[ib+1];
                ssmp[cc*576 + v] = sg0[v]*T0 + sg1[v]*T1 + sg2[v]*B0 + sg3[v]*B1;
            }
        }
        __syncthreads();
        #pragma unroll 4
        for (int r = 0; r < 36; r++) {
            ulonglong2 sv  = *(const ulonglong2*)&ssmp[r*64 + qp*4];
            ulonglong2 w01 = *(const ulonglong2*)&sdwd[r*128 + qo*8];
            ulonglong2 w23 = *(const ulonglong2*)&sdwd[r*128 + qo*8 + 4];
            FMA2(acc[0][0], w01.x, sv.x); FMA2(acc[0][1], w01.x, sv.y);
            FMA2(acc[1][0], w01.y, sv.x); FMA2(acc[1][1], w01.y, sv.y);
            FMA2(acc[2][0], w23.x, sv.x); FMA2(acc[2][1], w23.x, sv.y);
            FMA2(acc[3][0], w23.y, sv.x); FMA2(acc[3][1], w23.y, sv.y);
        }
        __syncthreads();
    }

    int wq = w0 + qp*4;
    #pragma unroll
    for (int i = 0; i < 4; i++) {
        int oc = qo*4 + i;
        float bb = db[oc];
        float a0,a1,a2,a3;
        unpack2(acc[i][0], a0, a1); unpack2(acc[i][1], a2, a3);
        float4 r = make_float4(a0+bb, a1+bb, a2+bb, a3+bb);
        *(float4*)&g_f[((size_t)(b*4*CO + br*CO + oc))*HW + h*WW + wq] = r;
    }
}

// ================= final 1x1 (256->64) + ReLU =================
__global__ void final_kernel(const float* __restrict__ cb, float* __restrict__ out)
{
    __shared__ __align__(16) float fs[1024];
    __shared__ __align__(16) float wsd[2048];
    int tid = threadIdx.x;
    int p0  = blockIdx.x*64;
    int b   = blockIdx.y;
    int qp = tid & 15, qo = tid >> 4;

    u64 acc[4][2];
    #pragma unroll
    for (int i = 0; i < 4; i++) { acc[i][0] = 0ull; acc[i][1] = 0ull; }

    for (int k0 = 0; k0 < 256; k0 += 16) {
        {
            int i = tid*4;
            int kk = i >> 6, px = i & 63;
            *(float4*)&fs[i] = *(const float4*)&g_f[((size_t)(b*256 + k0 + kk))*HW + p0 + px];
        }
        #pragma unroll 1
        for (int i = tid; i < 512; i += 256)
            *(float4*)&wsd[i*4] = *(const float4*)&g_cwtd[(size_t)k0*128 + i*4];
        __syncthreads();
        #pragma unroll
        for (int kk = 0; kk < 16; kk++) {
            ulonglong2 sv  = *(const ulonglong2*)&fs[kk*64 + qp*4];
            ulonglong2 w01 = *(const ulonglong2*)&wsd[kk*128 + qo*8];
            ulonglong2 w23 = *(const ulonglong2*)&wsd[kk*128 + qo*8 + 4];
            FMA2(acc[0][0], w01.x, sv.x); FMA2(acc[0][1], w01.x, sv.y);
            FMA2(acc[1][0], w01.y, sv.x); FMA2(acc[1][1], w01.y, sv.y);
            FMA2(acc[2][0], w23.x, sv.x); FMA2(acc[2][1], w23.x, sv.y);
            FMA2(acc[3][0], w23.y, sv.x); FMA2(acc[3][1], w23.y, sv.y);
        }
        __syncthreads();
    }

    int pp = p0 + qp*4;
    #pragma unroll
    for (int i = 0; i < 4; i++) {
        int oc = qo*4 + i;
        float bb = cb[oc];
        float a0,a1,a2,a3;
        unpack2(acc[i][0], a0, a1); unpack2(acc[i][1], a2, a3);
        float4 r = make_float4(fmaxf(a0+bb,0.f), fmaxf(a1+bb,0.f),
                               fmaxf(a2+bb,0.f), fmaxf(a3+bb,0.f));
        *(float4*)&out[((size_t)(b*CO + oc))*HW + pp] = r;
    }
}

// ================= launch =================
extern "C" void kernel_launch(void* const* d_in, const int* in_sizes, int n_in,
                              void* d_out, int out_size)
{
    const float* x   = (const float*)d_in[0];
    const float* w1  = (const float*)d_in[1];
    const float* b1  = (const float*)d_in[2];
    const float* w2  = (const float*)d_in[3];
    const float* b2  = (const float*)d_in[4];
    const float* w3  = (const float*)d_in[5];
    const float* b3  = (const float*)d_in[6];
    const float* w4  = (const float*)d_in[7];
    const float* b4  = (const float*)d_in[8];
    const float* p_w = (const float*)d_in[9];
    const float* p_b = (const float*)d_in[10];
    const float* dw  = (const float*)d_in[11];
    const float* db  = (const float*)d_in[12];
    const float* cw  = (const float*)d_in[13];
    const float* cb  = (const float*)d_in[14];
    float* out = (float*)d_out;

    prep1_kernel<<<256, 256>>>(w1, w2, w3, w4, p_w, dw, cw, b1, b2, b3, b4);
    prep2_kernel<<<4096, 256>>>(x);

    bconv_kernel<<<dim3(128, 4, 4), 256>>>();

    dim3 cblk(8, 16);
    offconv_kernel<<<dim3(4, 8, 32), cblk>>>(p_b);
    deform_kernel<<<dim3(2, 128, 16), 256>>>(db);
    final_kernel<<<dim3(256, 4), 256>>>(cb, out);
}

// round 5
// speedup vs baseline: 2.6633x; 1.4160x over previous
#include <cuda_runtime.h>
#include <cuda_bf16.h>
#include <cstdint>

#define BB 4
#define CIN 128
#define CO 64
#define HH 128
#define WW 128
#define HW (HH*WW)

#define PW 136
#define PH 130
#define PPLANE (PH*PW)

#define PLANE_WW 80
#define PLANE_RR 142
#define PLANE_SZ (PLANE_RR*PLANE_WW)

// ys planes (bf16 pair planes of branch features, halo 1): 130 rows x 68 u32
#define YSW 68
#define YSH 130
#define YSPLANE (YSH*YSW)

typedef unsigned long long u64;
typedef unsigned int u32;

__device__ __forceinline__ u32 smem_to_u32(const void* p) {
    u32 a; asm("{ .reg .u64 t; cvta.to.shared.u64 t, %1; cvt.u32.u64 %0, t; }" : "=r"(a) : "l"(p));
    return a;
}

#define MMA_BF16(d0,d1,d2,d3,a0,a1,a2,a3,b0,b1) \
    asm volatile("mma.sync.aligned.m16n8k16.row.col.f32.bf16.bf16.f32 " \
        "{%0,%1,%2,%3},{%4,%5,%6,%7},{%8,%9},{%0,%1,%2,%3};" \
        : "+f"(d0),"+f"(d1),"+f"(d2),"+f"(d3) \
        : "r"(a0),"r"(a1),"r"(a2),"r"(a3),"r"(b0),"r"(b1))

#define LDMATRIX_X4_TRANS(r0,r1,r2,r3,addr) \
    asm volatile("ldmatrix.sync.aligned.m8n8.x4.trans.shared.b16 {%0,%1,%2,%3},[%4];" \
        : "=r"(r0),"=r"(r1),"=r"(r2),"=r"(r3) : "r"(addr))

#define CVT_BF16X2(res, hi_f, lo_f) \
    asm("cvt.rn.bf16x2.f32 %0, %1, %2;" : "=r"(res) : "f"(hi_f), "f"(lo_f))

// ================= scratch =================
__device__ u32   g_xs [2*2*4*128*PLANE_SZ];   // [split][phase][b][ic] padded bf16-pair x planes
__device__ u32   g_wfA[4*72*8*32*4];          // branch A frags [br][ks][mb][lane][reg]
__device__ u32   g_dwf[36*8*32*4];            // dw A frags (M=128, k = n*64+c)
__device__ u32   g_pwf[36*4*32*4];            // p_w A frags (M=64)
__device__ u32   g_cwf[16*8*32*4];            // cw A frags (M=128)
__device__ float g_bias[4*64];
__device__ float g_yp [16*64*PPLANE];         // (br*4+b) padded fp32 features, zero ring
__device__ u32   g_ys [2*2*16*64*YSPLANE];    // bf16 split/phase pair planes of features
__device__ float g_off[16*18*HW];
__device__ u32   g_fs [2*4*256*8192];         // deform out: [split][b][ch256][px pairs]

// ================= prep 1: all weight fragments + bias + ring =================
__global__ void prep1_kernel(const float* __restrict__ w1, const float* __restrict__ w2,
                             const float* __restrict__ w3, const float* __restrict__ w4,
                             const float* __restrict__ pw, const float* __restrict__ dwp,
                             const float* __restrict__ cwp,
                             const float* __restrict__ b1, const float* __restrict__ b2,
                             const float* __restrict__ b3, const float* __restrict__ b4)
{
    int tid = blockIdx.x*blockDim.x + threadIdx.x;
    int nt  = gridDim.x*blockDim.x;
    const float* wb[4] = {w1,w2,w3,w4};
    const float* bbv[4] = {b1,b2,b3,b4};

    // branch conv A fragments (k = tap-major: ks = tap*8 + icc, 16 ic per step)
    for (int i = tid; i < 4*72*8*32*4; i += nt) {
        int br = i / 73728; int r2 = i % 73728;
        int ks = r2 >> 10;  int r3 = r2 & 1023;
        int mb = r3 >> 7;   int lane = (r3 >> 2) & 31; int reg = r3 & 3;
        int row = mb*16 + (lane>>2) + (reg&1)*8;
        int k0  = (lane&3)*2 + (reg>>1)*8;
        int oc = row & 63, split = row >> 6;
        int tap = ks >> 3;
        int ic0 = (ks & 7)*16;
        u32 out = 0;
        #pragma unroll
        for (int e = 0; e < 2; e++) {
            float W = wb[br][oc*1152 + (ic0 + k0 + e)*9 + tap];
            __nv_bfloat16 hi = __float2bfloat16(W);
            __nv_bfloat16 v = split ? __float2bfloat16(W - __bfloat162float(hi)) : hi;
            out |= (u32)__bfloat16_as_ushort(v) << (16*e);
        }
        g_wfA[i] = out;
    }
    // dw A fragments: K=576 with k = n*64 + c ; M=128 (dwh | dwl)
    for (int i = tid; i < 36*8*32*4; i += nt) {
        int ks = i >> 10; int r3 = i & 1023;
        int mb = r3 >> 7; int lane = (r3 >> 2) & 31; int reg = r3 & 3;
        int row = mb*16 + (lane>>2) + (reg&1)*8;
        int k0  = ks*16 + (lane&3)*2 + (reg>>1)*8;
        int oc = row & 63, split = row >> 6;
        u32 out = 0;
        #pragma unroll
        for (int e = 0; e < 2; e++) {
            int k = k0 + e; int c = k & 63; int n = k >> 6;
            float W = dwp[oc*576 + c*9 + n];
            __nv_bfloat16 hi = __float2bfloat16(W);
            __nv_bfloat16 v = split ? __float2bfloat16(W - __bfloat162float(hi)) : hi;
            out |= (u32)__bfloat16_as_ushort(v) << (16*e);
        }
        g_dwf[i] = out;
    }
    // p_w A fragments: M=64 (rows 0-31 hi(oc<18), 32-63 lo) ; k tap-major (36 ksteps, 4 icc)
    for (int i = tid; i < 36*4*32*4; i += nt) {
        int ks = i >> 9; int r3 = i & 511;
        int mb = r3 >> 7; int lane = (r3 >> 2) & 31; int reg = r3 & 3;
        int row = mb*16 + (lane>>2) + (reg&1)*8;
        int k0  = (lane&3)*2 + (reg>>1)*8;
        int oc = row & 31, split = row >> 5;
        int tap = ks >> 2;
        int ic0 = (ks & 3)*16;
        u32 out = 0;
        #pragma unroll
        for (int e = 0; e < 2; e++) {
            float W = (oc < 18) ? pw[oc*576 + (ic0 + k0 + e)*9 + tap] : 0.f;
            __nv_bfloat16 hi = __float2bfloat16(W);
            __nv_bfloat16 v = split ? __float2bfloat16(W - __bfloat162float(hi)) : hi;
            out |= (u32)__bfloat16_as_ushort(v) << (16*e);
        }
        g_pwf[i] = out;
    }
    // cw A fragments: M=128, K=256
    for (int i = tid; i < 16*8*32*4; i += nt) {
        int ks = i >> 10; int r3 = i & 1023;
        int mb = r3 >> 7; int lane = (r3 >> 2) & 31; int reg = r3 & 3;
        int row = mb*16 + (lane>>2) + (reg&1)*8;
        int k0  = ks*16 + (lane&3)*2 + (reg>>1)*8;
        int oc = row & 63, split = row >> 6;
        u32 out = 0;
        #pragma unroll
        for (int e = 0; e < 2; e++) {
            float W = cwp[oc*256 + k0 + e];
            __nv_bfloat16 hi = __float2bfloat16(W);
            __nv_bfloat16 v = split ? __float2bfloat16(W - __bfloat162float(hi)) : hi;
            out |= (u32)__bfloat16_as_ushort(v) << (16*e);
        }
        g_cwf[i] = out;
    }
    for (int i = tid; i < 256; i += nt) g_bias[i] = bbv[i>>6][i&63];
    // zero ring of all 1024 padded feature planes
    for (int i = tid; i < 1024*528; i += nt) {
        int p = i/528; int j = i - p*528;
        int r, c;
        if (j < 136)      { r = 0;       c = j; }
        else if (j < 272) { r = 129;     c = j - 136; }
        else if (j < 400) { r = j - 271; c = 3; }
        else              { r = j - 399; c = 132; }
        g_yp[(size_t)p*PPLANE + r*PW + c] = 0.f;
    }
}

// ================= prep 2: padded bf16 split/phase x planes =================
__global__ void prep2_kernel(const float* __restrict__ x)
{
    size_t total = (size_t)2*2*4*128*PLANE_SZ;
    size_t stride = (size_t)gridDim.x*blockDim.x;
    for (size_t i = (size_t)blockIdx.x*blockDim.x + threadIdx.x; i < total; i += stride) {
        int wd = (int)(i % PLANE_WW); size_t t = i / PLANE_WW;
        int rr = (int)(t % PLANE_RR); t /= PLANE_RR;
        int ic = (int)(t % 128); t /= 128;
        int b  = (int)(t % 4);   t /= 4;
        int phase = (int)(t & 1); int split = (int)(t >> 1);
        int row = rr - 7;
        int pxa = 2*wd + phase - 8;
        float va = 0.f, vb = 0.f;
        if ((unsigned)row < 128u) {
            const float* xr = x + ((size_t)(b*128+ic)*128 + row)*128;
            if ((unsigned)pxa < 128u)     va = xr[pxa];
            if ((unsigned)(pxa+1) < 128u) vb = xr[pxa+1];
        }
        __nv_bfloat16 ba, bbv;
        if (split == 0) { ba = __float2bfloat16(va); bbv = __float2bfloat16(vb); }
        else {
            ba  = __float2bfloat16(va - __bfloat162float(__float2bfloat16(va)));
            bbv = __float2bfloat16(vb - __bfloat162float(__float2bfloat16(vb)));
        }
        g_xs[i] = (u32)__bfloat16_as_ushort(ba) | ((u32)__bfloat16_as_ushort(bbv) << 16);
    }
}

// ================= branch conv (unchanged, proven) =================
__global__ void __launch_bounds__(256,2) bconv_kernel()
{
    __shared__ __align__(16) char sraw[33280];
    u32 sb = smem_to_u32(sraw);

    int tid = threadIdx.x, wid = tid>>5, lane = tid&31;
    int wm = wid & 3, nw = wid >> 2;
    int h = blockIdx.x, br = blockIdx.y, b = blockIdx.z;
    int D = 2*br + 1; float scale = (float)D;
    bool is_wh = (wm < 2);

    float acc[2][8][4];
    #pragma unroll
    for (int mi = 0; mi < 2; mi++)
        #pragma unroll
        for (int ni = 0; ni < 8; ni++)
            #pragma unroll
            for (int r = 0; r < 4; r++) acc[mi][ni][r] = 0.f;

    int lm_mat = lane >> 3, lm_row = lane & 7;
    int lm_k = (lm_mat & 1)*8 + lm_row;
    int lm_noff = (lm_mat >> 1)*8;

    auto loadB = [&](int ks, int buf) {
        int tap = ks >> 3, icc = ks & 7;
        int ky = tap/3 - 1, kx = tap - (tap/3)*3 - 1;
        int s = kx*D;
        int phase = (s + 8) & 1;
        int wd0 = (s + 8 - phase) >> 1;
        int srow = h + ky*D + 7;
        char* dst = sraw + buf*8704;
        #pragma unroll
        for (int i = 0; i < 8; i++) {
            int idx = tid + 256*i;
            int split = idx >> 10; int rem = idx & 1023;
            int ic = rem >> 6; int j = rem & 63;
            const u32* p = g_xs + ((size_t)((split*2+phase)*4 + b)*128 + icc*16 + ic)*PLANE_SZ
                         + (size_t)srow*PLANE_WW + wd0 + j;
            u32 v = __ldg(p);
            *(u32*)(dst + split*4352 + ic*272 + j*4) = v;
        }
    };

    loadB(0, 0);
    __syncthreads();

    for (int ks = 0; ks < 72; ks++) {
        int buf = ks & 1;
        if (ks + 1 < 72) loadB(ks+1, buf^1);

        u32 a0[2][4];
        {
            const uint4* ap = (const uint4*)(g_wfA + (((size_t)(br*72 + ks)*8 + wm*2)*32 + lane)*4);
            uint4 f0 = ap[0];
            uint4 f1 = ap[32];
            a0[0][0]=f0.x; a0[0][1]=f0.y; a0[0][2]=f0.z; a0[0][3]=f0.w;
            a0[1][0]=f1.x; a0[1][1]=f1.y; a0[1][2]=f1.z; a0[1][3]=f1.w;
        }

        int nsplits = is_wh ? 2 : 1;
        for (int sp = 0; sp < nsplits; sp++) {
            u32 bf[8][2];
            u32 base = sb + buf*8704 + sp*4352 + lm_k*272;
            #pragma unroll
            for (int li = 0; li < 4; li++) {
                int n = nw*64 + li*16 + lm_noff;
                u32 r0,r1,r2,r3;
                LDMATRIX_X4_TRANS(r0,r1,r2,r3, base + n*2);
                bf[2*li][0]=r0; bf[2*li][1]=r1; bf[2*li+1][0]=r2; bf[2*li+1][1]=r3;
            }
            #pragma unroll
            for (int mi = 0; mi < 2; mi++)
                #pragma unroll
                for (int ni = 0; ni < 8; ni++)
                    MMA_BF16(acc[mi][ni][0],acc[mi][ni][1],acc[mi][ni][2],acc[mi][ni][3],
                             a0[mi][0],a0[mi][1],a0[mi][2],a0[mi][3],
                             bf[ni][0],bf[ni][1]);
        }
        __syncthreads();
    }

    float* epi = (float*)sraw;
    if (!is_wh) {
        int pair = nw*2 + (wm - 2);
        #pragma unroll
        for (int mi = 0; mi < 2; mi++)
            #pragma unroll
            for (int ni = 0; ni < 8; ni++)
                *(float4*)&epi[pair*2048 + (mi*8+ni)*128 + lane*4] = *(float4*)acc[mi][ni];
    }
    __syncthreads();
    if (is_wh) {
        int pair = nw*2 + wm;
        int bi = br*4 + b;
        #pragma unroll
        for (int mi = 0; mi < 2; mi++) {
            #pragma unroll
            for (int ni = 0; ni < 8; ni++) {
                float4 part = *(float4*)&epi[pair*2048 + (mi*8+ni)*128 + lane*4];
                int oc = wm*32 + mi*16 + (lane>>2);
                int px = nw*64 + ni*8 + (lane&3)*2;
                float bb0 = g_bias[br*64 + oc];
                float bb8 = g_bias[br*64 + oc + 8];
                float* p0 = g_yp + ((size_t)(bi*64 + oc))*PPLANE + (size_t)(h+1)*PW + px + 4;
                float* p8 = p0 + (size_t)8*PPLANE;
                float2 o0, o8;
                o0.x = (acc[mi][ni][0] + part.x + bb0)*scale;
                o0.y = (acc[mi][ni][1] + part.y + bb0)*scale;
                o8.x = (acc[mi][ni][2] + part.z + bb8)*scale;
                o8.y = (acc[mi][ni][3] + part.w + bb8)*scale;
                *(float2*)p0 = o0;
                *(float2*)p8 = o8;
            }
        }
    }
}

// ================= ys convert: g_yp -> bf16 split/phase pair planes =================
__global__ void ysplit_kernel()
{
    size_t total = (size_t)2*2*16*64*YSPLANE;
    size_t stride = (size_t)gridDim.x*blockDim.x;
    for (size_t i = (size_t)blockIdx.x*blockDim.x + threadIdx.x; i < total; i += stride) {
        int wd = (int)(i % YSW); size_t t = i / YSW;
        int rr = (int)(t % YSH); t /= YSH;
        int ic = (int)(t % 64);  t /= 64;
        int bi = (int)(t % 16);  t /= 16;
        int phase = (int)(t & 1); int split = (int)(t >> 1);
        int x0 = 2*wd + phase - 2;
        const float* pl = g_yp + (size_t)(bi*64 + ic)*PPLANE + (size_t)rr*PW;
        float va = (x0 >= -1 && x0 <= 128) ? pl[x0 + 4] : 0.f;
        int x1 = x0 + 1;
        float vb = (x1 >= -1 && x1 <= 128) ? pl[x1 + 4] : 0.f;
        __nv_bfloat16 ba, bbv;
        if (split == 0) { ba = __float2bfloat16(va); bbv = __float2bfloat16(vb); }
        else {
            ba  = __float2bfloat16(va - __bfloat162float(__float2bfloat16(va)));
            bbv = __float2bfloat16(vb - __bfloat162float(__float2bfloat16(vb)));
        }
        g_ys[i] = (u32)__bfloat16_as_ushort(ba) | ((u32)__bfloat16_as_ushort(bbv) << 16);
    }
}

// ================= offset conv via MMA: 64->18, d=1, M=64(pwh|pwl) =================
// grid (128 h, 16 bi), 256 thr = 8 warps (4 wm x 2 nw); N=128 px; K=576 (36 ksteps)
__global__ void __launch_bounds__(256,2) offconv_kernel(const float* __restrict__ pb)
{
    __shared__ __align__(16) char sraw[17408];
    u32 sb = smem_to_u32(sraw);

    int tid = threadIdx.x, wid = tid>>5, lane = tid&31;
    int wm = wid & 3, nw = wid >> 2;
    int h = blockIdx.x, bi = blockIdx.y;
    bool is_wh = (wm < 2);

    float acc[8][4];
    #pragma unroll
    for (int ni = 0; ni < 8; ni++)
        #pragma unroll
        for (int r = 0; r < 4; r++) acc[ni][r] = 0.f;

    int lm_mat = lane >> 3, lm_row = lane & 7;
    int lm_k = (lm_mat & 1)*8 + lm_row;
    int lm_noff = (lm_mat >> 1)*8;

    auto loadB = [&](int ks, int buf) {
        int tap = ks >> 2, icc = ks & 3;
        int ky = tap/3 - 1, kx = tap - (tap/3)*3 - 1;
        int sph = kx + 2;
        int phase = sph & 1;
        int wd0 = (sph - phase) >> 1;
        int srow = h + ky + 1;
        char* dst = sraw + buf*8704;
        #pragma unroll
        for (int i = 0; i < 8; i++) {
            int idx = tid + 256*i;
            int split = idx >> 10; int rem = idx & 1023;
            int ic = rem >> 6; int j = rem & 63;
            const u32* p = g_ys + ((size_t)((split*2+phase)*16 + bi)*64 + icc*16 + ic)*YSPLANE
                         + (size_t)srow*YSW + wd0 + j;
            u32 v = __ldg(p);
            *(u32*)(dst + split*4352 + ic*272 + j*4) = v;
        }
    };

    loadB(0, 0);
    __syncthreads();

    for (int ks = 0; ks < 36; ks++) {
        int buf = ks & 1;
        if (ks + 1 < 36) loadB(ks+1, buf^1);

        u32 a0[4];
        {
            const uint4* ap = (const uint4*)(g_pwf + (((size_t)ks*4 + wm)*32 + lane)*4);
            uint4 f0 = ap[0];
            a0[0]=f0.x; a0[1]=f0.y; a0[2]=f0.z; a0[3]=f0.w;
        }

        int nsplits = is_wh ? 2 : 1;
        for (int sp = 0; sp < nsplits; sp++) {
            u32 bf[8][2];
            u32 base = sb + buf*8704 + sp*4352 + lm_k*272;
            #pragma unroll
            for (int li = 0; li < 4; li++) {
                int n = nw*64 + li*16 + lm_noff;
                u32 r0,r1,r2,r3;
                LDMATRIX_X4_TRANS(r0,r1,r2,r3, base + n*2);
                bf[2*li][0]=r0; bf[2*li][1]=r1; bf[2*li+1][0]=r2; bf[2*li+1][1]=r3;
            }
            #pragma unroll
            for (int ni = 0; ni < 8; ni++)
                MMA_BF16(acc[ni][0],acc[ni][1],acc[ni][2],acc[ni][3],
                         a0[0],a0[1],a0[2],a0[3],
                         bf[ni][0],bf[ni][1]);
        }
        __syncthreads();
    }

    float* epi = (float*)sraw;
    if (!is_wh) {
        int pair = nw*2 + (wm - 2);
        #pragma unroll
        for (int ni = 0; ni < 8; ni++)
            *(float4*)&epi[pair*1024 + ni*128 + lane*4] = *(float4*)acc[ni];
    }
    __syncthreads();
    if (is_wh) {
        int pair = nw*2 + wm;
        #pragma unroll
        for (int ni = 0; ni < 8; ni++) {
            float4 part = *(float4*)&epi[pair*1024 + ni*128 + lane*4];
            int oc = wm*16 + (lane>>2);
            int px = nw*64 + ni*8 + (lane&3)*2;
            if (oc < 18) {
                float bb = pb[oc];
                float2 o;
                o.x = acc[ni][0] + part.x + bb;
                o.y = acc[ni][1] + part.y + bb;
                *(float2*)&g_off[((size_t)(bi*18 + oc))*HW + h*WW + px] = o;
            }
            int oc8 = oc + 8;
            if (oc8 < 18) {
                float bb = pb[oc8];
                float2 o;
                o.x = acc[ni][2] + part.z + bb;
                o.y = acc[ni][3] + part.w + bb;
                *(float2*)&g_off[((size_t)(bi*18 + oc8))*HW + h*WW + px] = o;
            }
        }
    }
}

// ================= deform: gather (fp32) + MMA matmul (bf16 split) =================
// grid (2, 128, 16), 256 thr; per block 64 px, K=576 as 9 tap-chunks of 64 c-rows.
__global__ void __launch_bounds__(256,2) deform_kernel(const float* __restrict__ db)
{
    __shared__ int2   sidx2[576*2];              // (top,bot) per (n,px): [t] = {it, ib}
    __shared__ __align__(16) float4 sgw[576];
    __shared__ __align__(16) u32 smp[2*64*36];   // [split][c64][36 u32 row pitch 144B]
    u32 sb_smp = smem_to_u32(smp);

    int tid = threadIdx.x, wid = tid>>5, lane = tid&31;
    int wm = wid & 3, nw = wid >> 2;
    int w0 = blockIdx.x*64;
    int h  = blockIdx.y;
    int bi = blockIdx.z;
    int br = bi >> 2, b = bi & 3;
    bool is_wh = (wm < 2);

    // phase A: indices + bilinear weights
    #pragma unroll 1
    for (int t = tid; t < 576; t += 256) {
        int n = t / 64, px = t & 63;
        int wg = w0 + px;
        const float* offp = g_off + (((size_t)(bi*18 + n))*HH + h)*WW + wg;
        float offy = offp[0];
        float offx = offp[9*HW];
        float py  = (float)(h + 1)  + (float)(n/3) - 1.f + offy;
        float pxx = (float)(wg + 1) + (float)(n%3) - 1.f + offx;
        float fy = floorf(py), fx = floorf(pxx);
        float pyc = fminf(fmaxf(py,  0.f), 129.f);
        float pxc = fminf(fmaxf(pxx, 0.f), 129.f);
        float lty = fminf(fmaxf(fy,       0.f), 129.f);
        float rby = fminf(fmaxf(fy + 1.f, 0.f), 129.f);
        float ltx = fminf(fmaxf(fx,       0.f), 129.f);
        float rbx = fminf(fmaxf(fx + 1.f, 0.f), 129.f);
        float gy1 = 1.f + (lty - pyc), gy2 = 1.f - (rby - pyc);
        float gx1 = 1.f + (ltx - pxc), gx2 = 1.f - (rbx - pxc);
        if (!(fx >= 0.f && fx <= 128.f)) { gx1 = 0.f; gx2 = 0.f; }
        int x0b = min(max((int)fx, 0), 128);
        int y0 = (int)lty, y1 = (int)rby;
        sidx2[t] = make_int2(y0*PW + x0b + 3, y1*PW + x0b + 3);
        sgw[t] = make_float4(gy1*gx1, gy1*gx2, gy2*gx1, gy2*gx2);
    }

    int lm_mat = lane >> 3, lm_row = lane & 7;
    int lm_k = (lm_mat & 1)*8 + lm_row;
    int lm_noff = (lm_mat >> 1)*8;

    float acc[2][4][4];
    #pragma unroll
    for (int mi = 0; mi < 2; mi++)
        #pragma unroll
        for (int ni = 0; ni < 4; ni++)
            #pragma unroll
            for (int r = 0; r < 4; r++) acc[mi][ni][r] = 0.f;

    const float* ypb = g_yp + (size_t)bi*CO*PPLANE;
    __syncthreads();

    for (int n = 0; n < 9; n++) {
        // gather 64c x 64px, split to bf16 hi/lo pairs
        #pragma unroll 1
        for (int u = tid; u < 2048; u += 256) {
            int cc = u >> 5, pxw = u & 31;
            int t = n*64 + pxw*2;
            const float* bp = ypb + (size_t)cc*PPLANE;
            int2 i0 = sidx2[t];     float4 g0 = sgw[t];
            int2 i1 = sidx2[t+1];   float4 g1 = sgw[t+1];
            float v0 = g0.x*bp[i0.x] + g0.y*bp[i0.x+1] + g0.z*bp[i0.y] + g0.w*bp[i0.y+1];
            float v1 = g1.x*bp[i1.x] + g1.y*bp[i1.x+1] + g1.z*bp[i1.y] + g1.w*bp[i1.y+1];
            u32 hi01; CVT_BF16X2(hi01, v1, v0);
            float fh0 = __uint_as_float(hi01 << 16);
            float fh1 = __uint_as_float(hi01 & 0xFFFF0000u);
            u32 lo01; CVT_BF16X2(lo01, v1 - fh1, v0 - fh0);
            smp[cc*36 + pxw] = hi01;
            smp[64*36 + cc*36 + pxw] = lo01;
        }
        __syncthreads();

        #pragma unroll
        for (int kk = 0; kk < 4; kk++) {
            int ks = n*4 + kk;
            u32 a0[2][4];
            {
                const uint4* ap = (const uint4*)(g_dwf + (((size_t)ks*8 + wm*2)*32 + lane)*4);
                uint4 f0 = ap[0];
                uint4 f1 = ap[32];
                a0[0][0]=f0.x; a0[0][1]=f0.y; a0[0][2]=f0.z; a0[0][3]=f0.w;
                a0[1][0]=f1.x; a0[1][1]=f1.y; a0[1][2]=f1.z; a0[1][3]=f1.w;
            }
            int nsplits = is_wh ? 2 : 1;
            for (int sp = 0; sp < nsplits; sp++) {
                u32 bf[4][2];
                u32 base = sb_smp + sp*9216 + (kk*16 + lm_k)*144;
                #pragma unroll
                for (int li = 0; li < 2; li++) {
                    int nn = nw*32 + li*16 + lm_noff;
                    u32 r0,r1,r2,r3;
                    LDMATRIX_X4_TRANS(r0,r1,r2,r3, base + nn*2);
                    bf[2*li][0]=r0; bf[2*li][1]=r1; bf[2*li+1][0]=r2; bf[2*li+1][1]=r3;
                }
                #pragma unroll
                for (int mi = 0; mi < 2; mi++)
                    #pragma unroll
                    for (int ni = 0; ni < 4; ni++)
                        MMA_BF16(acc[mi][ni][0],acc[mi][ni][1],acc[mi][ni][2],acc[mi][ni][3],
                                 a0[mi][0],a0[mi][1],a0[mi][2],a0[mi][3],
                                 bf[ni][0],bf[ni][1]);
            }
        }
        __syncthreads();
    }

    // epilogue: combine hi+lo, add db, pack bf16 hi/lo pairs -> g_fs
    float* epi = (float*)smp;
    if (!is_wh) {
        int pair = nw*2 + (wm - 2);
        #pragma unroll
        for (int mi = 0; mi < 2; mi++)
            #pragma unroll
            for (int ni = 0; ni < 4; ni++)
                *(float4*)&epi[pair*1024 + (mi*4+ni)*128 + lane*4] = *(float4*)acc[mi][ni];
    }
    __syncthreads();
    if (is_wh) {
        int pair = nw*2 + wm;
        #pragma unroll
        for (int mi = 0; mi < 2; mi++) {
            #pragma unroll
            for (int ni = 0; ni < 4; ni++) {
                float4 part = *(float4*)&epi[pair*1024 + (mi*4+ni)*128 + lane*4];
                int oc = wm*32 + mi*16 + (lane>>2);
                int px = nw*32 + ni*8 + (lane&3)*2;
                float bb0 = db[oc];
                float bb8 = db[oc + 8];
                float v0 = acc[mi][ni][0] + part.x + bb0;
                float v1 = acc[mi][ni][1] + part.y + bb0;
                float v2 = acc[mi][ni][2] + part.z + bb8;
                float v3 = acc[mi][ni][3] + part.w + bb8;
                int wpair = (w0 + px) >> 1;
                size_t base0 = ((size_t)(b*256) + br*64 + oc)*8192 + (size_t)h*64 + wpair;
                size_t base8 = base0 + (size_t)8*8192;
                u32 hi01; CVT_BF16X2(hi01, v1, v0);
                float fh0 = __uint_as_float(hi01 << 16);
                float fh1 = __uint_as_float(hi01 & 0xFFFF0000u);
                u32 lo01; CVT_BF16X2(lo01, v1 - fh1, v0 - fh0);
                g_fs[base0] = hi01;
                g_fs[(size_t)4*256*8192 + base0] = lo01;
                u32 hi23; CVT_BF16X2(hi23, v3, v2);
                float fh2 = __uint_as_float(hi23 << 16);
                float fh3 = __uint_as_float(hi23 & 0xFFFF0000u);
                u32 lo23; CVT_BF16X2(lo23, v3 - fh3, v2 - fh2);
                g_fs[base8] = hi23;
                g_fs[(size_t)4*256*8192 + base8] = lo23;
            }
        }
    }
}

// ================= final 1x1 via MMA: 256->64 + ReLU =================
// grid (128 px-tiles, 4 b), 256 thr; N=128 px, K=256 (16 ksteps), M=128 (cwh|cwl)
__global__ void __launch_bounds__(256,2) final_kernel(const float* __restrict__ cb,
                                                      float* __restrict__ out)
{
    __shared__ __align__(16) char sraw[32768];
    u32 sb = smem_to_u32(sraw);

    int tid = threadIdx.x, wid = tid>>5, lane = tid&31;
    int wm = wid & 3, nw = wid >> 2;
    int pt = blockIdx.x, b = blockIdx.y;
    int p0w = pt*64;                 // u32-pair base (128 px)
    bool is_wh = (wm < 2);

    float acc[2][8][4];
    #pragma unroll
    for (int mi = 0; mi < 2; mi++)
        #pragma unroll
        for (int ni = 0; ni < 8; ni++)
            #pragma unroll
            for (int r = 0; r < 4; r++) acc[mi][ni][r] = 0.f;

    int lm_mat = lane >> 3, lm_row = lane & 7;
    int lm_k = (lm_mat & 1)*8 + lm_row;
    int lm_noff = (lm_mat >> 1)*8;

    auto loadB = [&](int ks, int buf) {
        char* dst = sraw + buf*8704;
        #pragma unroll
        for (int i = 0; i < 8; i++) {
            int idx = tid + 256*i;
            int split = idx >> 10; int rem = idx & 1023;
            int kr = rem >> 6; int j = rem & 63;
            const u32* p = g_fs + ((size_t)(split*4 + b)*256 + ks*16 + kr)*8192 + p0w + j;
            u32 v = __ldg(p);
            *(u32*)(dst + split*4352 + kr*272 + j*4) = v;
        }
    };

    loadB(0, 0);
    __syncthreads();

    for (int ks = 0; ks < 16; ks++) {
        int buf = ks & 1;
        if (ks + 1 < 16) loadB(ks+1, buf^1);

        u32 a0[2][4];
        {
            const uint4* ap = (const uint4*)(g_cwf + (((size_t)ks*8 + wm*2)*32 + lane)*4);
            uint4 f0 = ap[0];
            uint4 f1 = ap[32];
            a0[0][0]=f0.x; a0[0][1]=f0.y; a0[0][2]=f0.z; a0[0][3]=f0.w;
            a0[1][0]=f1.x; a0[1][1]=f1.y; a0[1][2]=f1.z; a0[1][3]=f1.w;
        }

        int nsplits = is_wh ? 2 : 1;
        for (int sp = 0; sp < nsplits; sp++) {
            u32 bf[8][2];
            u32 base = sb + buf*8704 + sp*4352 + lm_k*272;
            #pragma unroll
            for (int li = 0; li < 4; li++) {
                int n = nw*64 + li*16 + lm_noff;
                u32 r0,r1,r2,r3;
                LDMATRIX_X4_TRANS(r0,r1,r2,r3, base + n*2);
                bf[2*li][0]=r0; bf[2*li][1]=r1; bf[2*li+1][0]=r2; bf[2*li+1][1]=r3;
            }
            #pragma unroll
            for (int mi = 0; mi < 2; mi++)
                #pragma unroll
                for (int ni = 0; ni < 8; ni++)
                    MMA_BF16(acc[mi][ni][0],acc[mi][ni][1],acc[mi][ni][2],acc[mi][ni][3],
                             a0[mi][0],a0[mi][1],a0[mi][2],a0[mi][3],
                             bf[ni][0],bf[ni][1]);
        }
        __syncthreads();
    }

    float* epi = (float*)sraw;
    if (!is_wh) {
        int pair = nw*2 + (wm - 2);
        #pragma unroll
        for (int mi = 0; mi < 2; mi++)
            #pragma unroll
            for (int ni = 0; ni < 8; ni++)
                *(float4*)&epi[pair*2048 + (mi*8+ni)*128 + lane*4] = *(float4*)acc[mi][ni];
    }
    __syncthreads();
    if (is_wh) {
        int pair = nw*2 + wm;
        #pragma unroll
        for (int mi = 0; mi < 2; mi++) {
            #pragma unroll
            for (int ni = 0; ni < 8; ni++) {
                float4 part = *(float4*)&epi[pair*2048 + (mi*8+ni)*128 + lane*4];
                int oc = wm*32 + mi*16 + (lane>>2);
                int px = nw*64 + ni*8 + (lane&3)*2;
                float bb0 = cb[oc];
                float bb8 = cb[oc + 8];
                float2 o0, o8;
                o0.x = fmaxf(acc[mi][ni][0] + part.x + bb0, 0.f);
                o0.y = fmaxf(acc[mi][ni][1] + part.y + bb0, 0.f);
                o8.x = fmaxf(acc[mi][ni][2] + part.z + bb8, 0.f);
                o8.y = fmaxf(acc[mi][ni][3] + part.w + bb8, 0.f);
                float* q0 = out + ((size_t)(b*64 + oc))*HW + p0w*2 + px;
                float* q8 = q0 + (size_t)8*HW;
                *(float2*)q0 = o0;
                *(float2*)q8 = o8;
            }
        }
    }
}

// ================= launch =================
extern "C" void kernel_launch(void* const* d_in, const int* in_sizes, int n_in,
                              void* d_out, int out_size)
{
    const float* x   = (const float*)d_in[0];
    const float* w1  = (const float*)d_in[1];
    const float* b1  = (const float*)d_in[2];
    const float* w2  = (const float*)d_in[3];
    const float* b2  = (const float*)d_in[4];
    const float* w3  = (const float*)d_in[5];
    const float* b3  = (const float*)d_in[6];
    const float* w4  = (const float*)d_in[7];
    const float* b4  = (const float*)d_in[8];
    const float* p_w = (const float*)d_in[9];
    const float* p_b = (const float*)d_in[10];
    const float* dw  = (const float*)d_in[11];
    const float* db  = (const float*)d_in[12];
    const float* cw  = (const float*)d_in[13];
    const float* cb  = (const float*)d_in[14];
    float* out = (float*)d_out;

    prep1_kernel<<<256, 256>>>(w1, w2, w3, w4, p_w, dw, cw, b1, b2, b3, b4);
    prep2_kernel<<<4096, 256>>>(x);
    bconv_kernel<<<dim3(128, 4, 4), 256>>>();
    ysplit_kernel<<<8192, 256>>>();
    offconv_kernel<<<dim3(128, 16), 256>>>(p_b);
    deform_kernel<<<dim3(2, 128, 16), 256>>>(db);
    final_kernel<<<dim3(128, 4), 256>>>(cb, out);
}